// round 5
// baseline (speedup 1.0000x reference)
#include <cuda_runtime.h>

#define B_ 64
#define J_ 25
#define V_ 50000
#define VT 64           // threads per skin block
#define VPT 4           // vertices per thread (consecutive; V_%4==0)
#define VT2 (VT*VPT)    // 256 vertices per block
#define NB 8            // batches per skin block
#define NPAIR (NB/2)
#define WSTR 260        // transposed-weight row stride (mult of 4 -> 16B-aligned rows)
#define BPB 32          // batches per fk block

// Scratch (device global; no allocation allowed)
__device__ float g_T[B_*J_*12];   // per-(b,j) skinning transform (3x4 row-major)

// ---------------------------------------------------------------------------
// FK kernel: 2 blocks x 1024 threads, 32 batches per block. Locals in smem,
// 96 threads run the sequential chain with smem-only reads.
// ---------------------------------------------------------------------------
__global__ __launch_bounds__(1024)
void fk_kernel(const float* __restrict__ je,
               const float* __restrict__ lp,
               const float* __restrict__ sc,
               const float* __restrict__ gpi,
               const int* __restrict__ parents,
               float* __restrict__ joint_out) {
    __shared__ float ls[BPB * J_ * 12];
    __shared__ float gpis[J_ * 16];
    __shared__ int   par[J_];

    int tid = threadIdx.x;
    int bbase = blockIdx.x * BPB;

    if (tid < J_ * 16) gpis[tid] = gpi[tid];
    if (tid < J_) par[tid] = parents[tid];

    for (int idx = tid; idx < BPB * J_; idx += blockDim.x) {
        int j = idx % J_;
        int gidx = bbase * J_ + idx;
        float ex = je[gidx*3+0], ey = je[gidx*3+1], ez = je[gidx*3+2];
        float sx, cx, sy, cy, sz, cz;
        sincosf(ex, &sx, &cx);
        sincosf(ey, &sy, &cy);
        sincosf(ez, &sz, &cz);
        float R00 = cz*cy, R01 = cz*sy*sx - sz*cx, R02 = cz*sy*cx + sz*sx;
        float R10 = sz*cy, R11 = sz*sy*sx + cz*cx, R12 = sz*sy*cx - cz*sx;
        float R20 = -sy,   R21 = cy*sx,            R22 = cy*cx;
        const float* L0 = lp + j*16;
        float* out = ls + idx*12;
        #pragma unroll
        for (int r = 0; r < 3; ++r) {
            float a0 = L0[r*4+0], a1 = L0[r*4+1], a2 = L0[r*4+2];
            out[r*4+0] = a0*R00 + a1*R10 + a2*R20;
            out[r*4+1] = a0*R01 + a1*R11 + a2*R21;
            out[r*4+2] = a0*R02 + a1*R12 + a2*R22;
            out[r*4+3] = L0[r*4+3] + sc[j*3+r];
        }
    }

    __syncthreads();

    if (tid >= BPB * 3) return;
    int bl = tid / 3, r = tid % 3;
    int b = bbase + bl;

    float Grow[J_][4];
    float pr0 = 0.f, pr1 = 0.f, pr2 = 0.f, pr3 = 0.f;
    int prevj = -2;
    for (int j = 0; j < J_; ++j) {
        int pj = par[j];
        float g0, g1, g2, g3;
        if (pj < 0) {
            g0 = (r == 0) ? 1.f : 0.f;
            g1 = (r == 1) ? 1.f : 0.f;
            g2 = (r == 2) ? 1.f : 0.f;
            g3 = 0.f;
        } else {
            float p0, p1, p2, p3;
            if (pj == prevj) { p0 = pr0; p1 = pr1; p2 = pr2; p3 = pr3; }
            else { p0 = Grow[pj][0]; p1 = Grow[pj][1]; p2 = Grow[pj][2]; p3 = Grow[pj][3]; }
            const float* L = ls + (bl*J_ + j) * 12;
            g0 = p0*L[0] + p1*L[4] + p2*L[8];
            g1 = p0*L[1] + p1*L[5] + p2*L[9];
            g2 = p0*L[2] + p1*L[6] + p2*L[10];
            g3 = p0*L[3] + p1*L[7] + p2*L[11] + p3;
        }
        Grow[j][0] = g0; Grow[j][1] = g1; Grow[j][2] = g2; Grow[j][3] = g3;
        pr0 = g0; pr1 = g1; pr2 = g2; pr3 = g3; prevj = j;

        const float* P = gpis + j*16;
        float4 t4;
        t4.x = g0*P[0] + g1*P[4] + g2*P[8];
        t4.y = g0*P[1] + g1*P[5] + g2*P[9];
        t4.z = g0*P[2] + g1*P[6] + g2*P[10];
        t4.w = g0*P[3] + g1*P[7] + g2*P[11] + g3;
        *reinterpret_cast<float4*>(g_T + (b*J_ + j)*12 + r*4) = t4;
        joint_out[(b*J_ + j)*3 + r] = g3;
    }
}

// ---------------------------------------------------------------------------
// f32x2 packed helpers (sm_100+)
// ---------------------------------------------------------------------------
__device__ __forceinline__ unsigned long long pack2(float lo, float hi) {
    unsigned long long d;
    asm("mov.b64 %0, {%1, %2};" : "=l"(d)
        : "r"(__float_as_uint(lo)), "r"(__float_as_uint(hi)));
    return d;
}
__device__ __forceinline__ unsigned long long pack2s(float w) {
    unsigned long long d;
    asm("mov.b64 %0, {%1, %1};" : "=l"(d) : "r"(__float_as_uint(w)));
    return d;
}
__device__ __forceinline__ void unpack2(unsigned long long s, float& lo, float& hi) {
    unsigned int a, b;
    asm("mov.b64 {%0, %1}, %2;" : "=r"(a), "=r"(b) : "l"(s));
    lo = __uint_as_float(a); hi = __uint_as_float(b);
}
__device__ __forceinline__ void fma2acc(unsigned long long& d,
                                        unsigned long long a,
                                        unsigned long long b) {
    asm("fma.rn.f32x2 %0, %1, %2, %0;" : "+l"(d) : "l"(a), "l"(b));
}
__device__ __forceinline__ unsigned long long fma2(unsigned long long a,
                                                   unsigned long long b,
                                                   unsigned long long c) {
    unsigned long long d;
    asm("fma.rn.f32x2 %0, %1, %2, %3;" : "=l"(d) : "l"(a), "l"(b), "l"(c));
    return d;
}

// ---------------------------------------------------------------------------
// Skinning kernel. 64 threads x 4 consecutive vertices/thread = 256 vertices
// per block, x 8 batches (4 batch pairs). Accumulators are f32x2 packed over
// the batch pair; each broadcast T LDS.128 feeds FOUR vertices (48 FFMA2 per
// 7 LDS per joint -> fma-bound). Weights: one LDS.128 per (joint,thread)
// from transposed smem (tid*16B -> phase-conflict-free).
// Static smem 35.7KB < 48KB; 6 blocks/SM -> 12 warps.
// ---------------------------------------------------------------------------
__global__ __launch_bounds__(VT, 6)
void skin_kernel(const float* __restrict__ vtx,
                 const float* __restrict__ W,
                 const float* __restrict__ pc,
                 const float* __restrict__ ic,
                 float* __restrict__ mesh_out) {
    __shared__ float ws_t[J_ * WSTR];                     // 26.0 KB, transposed
    __shared__ __align__(16) float2 Ts[NPAIR * J_ * 12];  // 9.6 KB

    int tid = threadIdx.x;
    int v0 = blockIdx.x * VT2;
    int b0base = blockIdx.y * NB;
    int nv = min(VT2, V_ - v0);   // V_%4==0 -> nv%4==0

    // Stage weights transposed: ws_t[j*WSTR + vv] = W[v0+vv][j]
    for (int i = tid; i < nv * J_; i += VT) {
        int vv = i / J_;
        int j  = i - vv * J_;
        ws_t[j * WSTR + vv] = W[(size_t)v0 * J_ + i];
    }
    // Stage T for NB batches, interleaved per batch pair
    for (int i = tid; i < NPAIR * J_ * 12; i += VT) {
        int p = i / (J_ * 12);
        int rem = i - p * (J_ * 12);
        int b0 = b0base + 2 * p;
        Ts[i] = make_float2(g_T[b0 * (J_*12) + rem],
                            g_T[(b0 + 1) * (J_*12) + rem]);
    }
    __syncthreads();

    int lv = VPT * tid;            // local vertex base
    if (lv >= nv) return;          // all-or-nothing (nv%4==0)
    int vA = v0 + lv;

    // Vertex coords: 12 consecutive floats, 16B aligned (vA%4==0)
    float vc[12];
    *reinterpret_cast<float4*>(vc + 0) = *reinterpret_cast<const float4*>(vtx + (size_t)vA*3 + 0);
    *reinterpret_cast<float4*>(vc + 4) = *reinterpret_cast<const float4*>(vtx + (size_t)vA*3 + 4);
    *reinterpret_cast<float4*>(vc + 8) = *reinterpret_cast<const float4*>(vtx + (size_t)vA*3 + 8);

    const size_t strideB = (size_t)V_ * 3;
    const size_t base = (size_t)b0base * strideB + (size_t)vA * 3;

    #pragma unroll 1
    for (int p = 0; p < NPAIR; ++p) {
        unsigned long long M[VPT][12];
        #pragma unroll
        for (int vv = 0; vv < VPT; ++vv)
            #pragma unroll
            for (int k = 0; k < 12; ++k) M[vv][k] = 0ull;

        const ulonglong2* tb =
            reinterpret_cast<const ulonglong2*>(Ts + p * (J_ * 12));
        const float* wb = ws_t + lv;

        #pragma unroll 5
        for (int j = 0; j < J_; ++j) {
            float4 w4 = *reinterpret_cast<const float4*>(wb + j * WSTR);
            unsigned long long wp0 = pack2s(w4.x);
            unsigned long long wp1 = pack2s(w4.y);
            unsigned long long wp2 = pack2s(w4.z);
            unsigned long long wp3 = pack2s(w4.w);
            const ulonglong2* trow = tb + j * 6;   // 12 float2 = 6 x 16B
            #pragma unroll
            for (int m = 0; m < 6; ++m) {
                ulonglong2 q = trow[m];
                fma2acc(M[0][2*m], q.x, wp0); fma2acc(M[0][2*m+1], q.y, wp0);
                fma2acc(M[1][2*m], q.x, wp1); fma2acc(M[1][2*m+1], q.y, wp1);
                fma2acc(M[2][2*m], q.x, wp2); fma2acc(M[2][2*m+1], q.y, wp2);
                fma2acc(M[3][2*m], q.x, wp3); fma2acc(M[3][2*m+1], q.y, wp3);
            }
        }

        size_t o0 = base + (size_t)(2 * p) * strideB;   // batch b0: 12 floats
        size_t o1 = o0 + strideB;                       // batch b1

        // Correctives: 12 consecutive floats per (array,batch), 16B aligned
        float c0[12], c1[12], i0[12], i1[12];
        #pragma unroll
        for (int q4 = 0; q4 < 3; ++q4) {
            *reinterpret_cast<float4*>(c0 + 4*q4) = *reinterpret_cast<const float4*>(pc + o0 + 4*q4);
            *reinterpret_cast<float4*>(c1 + 4*q4) = *reinterpret_cast<const float4*>(pc + o1 + 4*q4);
            *reinterpret_cast<float4*>(i0 + 4*q4) = *reinterpret_cast<const float4*>(ic + o0 + 4*q4);
            *reinterpret_cast<float4*>(i1 + 4*q4) = *reinterpret_cast<const float4*>(ic + o1 + 4*q4);
        }

        float r0[12], r1[12];   // results per batch, 12 consecutive floats
        #pragma unroll
        for (int vv = 0; vv < VPT; ++vv) {
            unsigned long long px = pack2(vc[3*vv+0] + c0[3*vv+0] + i0[3*vv+0],
                                          vc[3*vv+0] + c1[3*vv+0] + i1[3*vv+0]);
            unsigned long long py = pack2(vc[3*vv+1] + c0[3*vv+1] + i0[3*vv+1],
                                          vc[3*vv+1] + c1[3*vv+1] + i1[3*vv+1]);
            unsigned long long pz = pack2(vc[3*vv+2] + c0[3*vv+2] + i0[3*vv+2],
                                          vc[3*vv+2] + c1[3*vv+2] + i1[3*vv+2]);
            #pragma unroll
            for (int r = 0; r < 3; ++r) {
                unsigned long long o = M[vv][4*r + 3];
                o = fma2(M[vv][4*r + 2], pz, o);
                o = fma2(M[vv][4*r + 1], py, o);
                o = fma2(M[vv][4*r + 0], px, o);
                unpack2(o, r0[3*vv + r], r1[3*vv + r]);
            }
        }

        #pragma unroll
        for (int q4 = 0; q4 < 3; ++q4) {
            *reinterpret_cast<float4*>(mesh_out + o0 + 4*q4) = *reinterpret_cast<float4*>(r0 + 4*q4);
            *reinterpret_cast<float4*>(mesh_out + o1 + 4*q4) = *reinterpret_cast<float4*>(r1 + 4*q4);
        }
    }
}

// ---------------------------------------------------------------------------
extern "C" void kernel_launch(void* const* d_in, const int* in_sizes, int n_in,
                              void* d_out, int out_size) {
    const float* joint_euler = (const float*)d_in[0];
    const float* vtx         = (const float*)d_in[1];
    const float* W           = (const float*)d_in[2];
    const float* local_pose  = (const float*)d_in[3];
    const float* gpi         = (const float*)d_in[4];
    const float* sc          = (const float*)d_in[5];
    const float* pc          = (const float*)d_in[6];
    const float* ic          = (const float*)d_in[7];
    const int*   parents     = (const int*)d_in[8];
    float* out = (float*)d_out;

    fk_kernel<<<B_ / BPB, 1024>>>(joint_euler, local_pose, sc, gpi, parents, out);
    dim3 grid((V_ + VT2 - 1) / VT2, B_ / NB);
    skin_kernel<<<grid, VT>>>(vtx, W, pc, ic, out + B_*J_*3);
}

// round 6
// speedup vs baseline: 1.0044x; 1.0044x over previous
#include <cuda_runtime.h>

#define B_ 64
#define J_ 25
#define V_ 50000
#define VT 64           // threads per skin block
#define VPT 4           // vertices per thread (consecutive; V_%4==0)
#define VT2 (VT*VPT)    // 256 vertices per block
#define NB 8            // batches per skin block
#define NPAIR (NB/2)
#define WSTR 260        // transposed-weight row stride (mult of 4 -> 16B-aligned rows)
#define BPB 32          // batches per fk block

// Scratch (device global; no allocation allowed)
__device__ float g_T[B_*J_*12];   // per-(b,j) skinning transform (3x4 row-major)

// ---------------------------------------------------------------------------
// FK kernel: 2 blocks x 1024 threads, 32 batches per block. Locals in smem,
// 96 threads run the sequential chain with smem-only reads.
// ---------------------------------------------------------------------------
__global__ __launch_bounds__(1024)
void fk_kernel(const float* __restrict__ je,
               const float* __restrict__ lp,
               const float* __restrict__ sc,
               const float* __restrict__ gpi,
               const int* __restrict__ parents,
               float* __restrict__ joint_out) {
    __shared__ float ls[BPB * J_ * 12];
    __shared__ float gpis[J_ * 16];
    __shared__ int   par[J_];

    int tid = threadIdx.x;
    int bbase = blockIdx.x * BPB;

    if (tid < J_ * 16) gpis[tid] = gpi[tid];
    if (tid < J_) par[tid] = parents[tid];

    for (int idx = tid; idx < BPB * J_; idx += blockDim.x) {
        int j = idx % J_;
        int gidx = bbase * J_ + idx;
        float ex = je[gidx*3+0], ey = je[gidx*3+1], ez = je[gidx*3+2];
        float sx, cx, sy, cy, sz, cz;
        sincosf(ex, &sx, &cx);
        sincosf(ey, &sy, &cy);
        sincosf(ez, &sz, &cz);
        float R00 = cz*cy, R01 = cz*sy*sx - sz*cx, R02 = cz*sy*cx + sz*sx;
        float R10 = sz*cy, R11 = sz*sy*sx + cz*cx, R12 = sz*sy*cx - cz*sx;
        float R20 = -sy,   R21 = cy*sx,            R22 = cy*cx;
        const float* L0 = lp + j*16;
        float* out = ls + idx*12;
        #pragma unroll
        for (int r = 0; r < 3; ++r) {
            float a0 = L0[r*4+0], a1 = L0[r*4+1], a2 = L0[r*4+2];
            out[r*4+0] = a0*R00 + a1*R10 + a2*R20;
            out[r*4+1] = a0*R01 + a1*R11 + a2*R21;
            out[r*4+2] = a0*R02 + a1*R12 + a2*R22;
            out[r*4+3] = L0[r*4+3] + sc[j*3+r];
        }
    }

    __syncthreads();

    if (tid >= BPB * 3) return;
    int bl = tid / 3, r = tid % 3;
    int b = bbase + bl;

    float Grow[J_][4];
    float pr0 = 0.f, pr1 = 0.f, pr2 = 0.f, pr3 = 0.f;
    int prevj = -2;
    for (int j = 0; j < J_; ++j) {
        int pj = par[j];
        float g0, g1, g2, g3;
        if (pj < 0) {
            g0 = (r == 0) ? 1.f : 0.f;
            g1 = (r == 1) ? 1.f : 0.f;
            g2 = (r == 2) ? 1.f : 0.f;
            g3 = 0.f;
        } else {
            float p0, p1, p2, p3;
            if (pj == prevj) { p0 = pr0; p1 = pr1; p2 = pr2; p3 = pr3; }
            else { p0 = Grow[pj][0]; p1 = Grow[pj][1]; p2 = Grow[pj][2]; p3 = Grow[pj][3]; }
            const float* L = ls + (bl*J_ + j) * 12;
            g0 = p0*L[0] + p1*L[4] + p2*L[8];
            g1 = p0*L[1] + p1*L[5] + p2*L[9];
            g2 = p0*L[2] + p1*L[6] + p2*L[10];
            g3 = p0*L[3] + p1*L[7] + p2*L[11] + p3;
        }
        Grow[j][0] = g0; Grow[j][1] = g1; Grow[j][2] = g2; Grow[j][3] = g3;
        pr0 = g0; pr1 = g1; pr2 = g2; pr3 = g3; prevj = j;

        const float* P = gpis + j*16;
        float4 t4;
        t4.x = g0*P[0] + g1*P[4] + g2*P[8];
        t4.y = g0*P[1] + g1*P[5] + g2*P[9];
        t4.z = g0*P[2] + g1*P[6] + g2*P[10];
        t4.w = g0*P[3] + g1*P[7] + g2*P[11] + g3;
        *reinterpret_cast<float4*>(g_T + (b*J_ + j)*12 + r*4) = t4;
        joint_out[(b*J_ + j)*3 + r] = g3;
    }
}

// ---------------------------------------------------------------------------
// f32x2 packed helpers (sm_100+)
// ---------------------------------------------------------------------------
__device__ __forceinline__ unsigned long long pack2(float lo, float hi) {
    unsigned long long d;
    asm("mov.b64 %0, {%1, %2};" : "=l"(d)
        : "r"(__float_as_uint(lo)), "r"(__float_as_uint(hi)));
    return d;
}
__device__ __forceinline__ unsigned long long pack2s(float w) {
    unsigned long long d;
    asm("mov.b64 %0, {%1, %1};" : "=l"(d) : "r"(__float_as_uint(w)));
    return d;
}
__device__ __forceinline__ void unpack2(unsigned long long s, float& lo, float& hi) {
    unsigned int a, b;
    asm("mov.b64 {%0, %1}, %2;" : "=r"(a), "=r"(b) : "l"(s));
    lo = __uint_as_float(a); hi = __uint_as_float(b);
}
__device__ __forceinline__ void fma2acc(unsigned long long& d,
                                        unsigned long long a,
                                        unsigned long long b) {
    asm("fma.rn.f32x2 %0, %1, %2, %0;" : "+l"(d) : "l"(a), "l"(b));
}
__device__ __forceinline__ unsigned long long fma2(unsigned long long a,
                                                   unsigned long long b,
                                                   unsigned long long c) {
    unsigned long long d;
    asm("fma.rn.f32x2 %0, %1, %2, %3;" : "=l"(d) : "l"(a), "l"(b), "l"(c));
    return d;
}

// ---------------------------------------------------------------------------
// Skinning kernel. 64 threads x 4 consecutive vertices/thread = 256 vertices
// per block, x 8 batches (4 batch pairs). Accumulators are f32x2 packed over
// the batch pair; each broadcast T LDS.128 feeds FOUR vertices (48 FFMA2 per
// 7 LDS per joint -> fma-bound). Weights: one LDS.128 per (joint,thread)
// from transposed smem (tid*16B -> phase-conflict-free).
// Static smem 35.7KB < 48KB; 6 blocks/SM -> 12 warps.
// ---------------------------------------------------------------------------
__global__ __launch_bounds__(VT, 6)
void skin_kernel(const float* __restrict__ vtx,
                 const float* __restrict__ W,
                 const float* __restrict__ pc,
                 const float* __restrict__ ic,
                 float* __restrict__ mesh_out) {
    __shared__ float ws_t[J_ * WSTR];                     // 26.0 KB, transposed
    __shared__ __align__(16) float2 Ts[NPAIR * J_ * 12];  // 9.6 KB

    int tid = threadIdx.x;
    int v0 = blockIdx.x * VT2;
    int b0base = blockIdx.y * NB;
    int nv = min(VT2, V_ - v0);   // V_%4==0 -> nv%4==0

    // Stage weights transposed: ws_t[j*WSTR + vv] = W[v0+vv][j]
    for (int i = tid; i < nv * J_; i += VT) {
        int vv = i / J_;
        int j  = i - vv * J_;
        ws_t[j * WSTR + vv] = W[(size_t)v0 * J_ + i];
    }
    // Stage T for NB batches, interleaved per batch pair
    for (int i = tid; i < NPAIR * J_ * 12; i += VT) {
        int p = i / (J_ * 12);
        int rem = i - p * (J_ * 12);
        int b0 = b0base + 2 * p;
        Ts[i] = make_float2(g_T[b0 * (J_*12) + rem],
                            g_T[(b0 + 1) * (J_*12) + rem]);
    }
    __syncthreads();

    int lv = VPT * tid;            // local vertex base
    if (lv >= nv) return;          // all-or-nothing (nv%4==0)
    int vA = v0 + lv;

    // Vertex coords: 12 consecutive floats, 16B aligned (vA%4==0)
    float vc[12];
    *reinterpret_cast<float4*>(vc + 0) = *reinterpret_cast<const float4*>(vtx + (size_t)vA*3 + 0);
    *reinterpret_cast<float4*>(vc + 4) = *reinterpret_cast<const float4*>(vtx + (size_t)vA*3 + 4);
    *reinterpret_cast<float4*>(vc + 8) = *reinterpret_cast<const float4*>(vtx + (size_t)vA*3 + 8);

    const size_t strideB = (size_t)V_ * 3;
    const size_t base = (size_t)b0base * strideB + (size_t)vA * 3;

    #pragma unroll 1
    for (int p = 0; p < NPAIR; ++p) {
        unsigned long long M[VPT][12];
        #pragma unroll
        for (int vv = 0; vv < VPT; ++vv)
            #pragma unroll
            for (int k = 0; k < 12; ++k) M[vv][k] = 0ull;

        const ulonglong2* tb =
            reinterpret_cast<const ulonglong2*>(Ts + p * (J_ * 12));
        const float* wb = ws_t + lv;

        #pragma unroll 5
        for (int j = 0; j < J_; ++j) {
            float4 w4 = *reinterpret_cast<const float4*>(wb + j * WSTR);
            unsigned long long wp0 = pack2s(w4.x);
            unsigned long long wp1 = pack2s(w4.y);
            unsigned long long wp2 = pack2s(w4.z);
            unsigned long long wp3 = pack2s(w4.w);
            const ulonglong2* trow = tb + j * 6;   // 12 float2 = 6 x 16B
            #pragma unroll
            for (int m = 0; m < 6; ++m) {
                ulonglong2 q = trow[m];
                fma2acc(M[0][2*m], q.x, wp0); fma2acc(M[0][2*m+1], q.y, wp0);
                fma2acc(M[1][2*m], q.x, wp1); fma2acc(M[1][2*m+1], q.y, wp1);
                fma2acc(M[2][2*m], q.x, wp2); fma2acc(M[2][2*m+1], q.y, wp2);
                fma2acc(M[3][2*m], q.x, wp3); fma2acc(M[3][2*m+1], q.y, wp3);
            }
        }

        size_t o0 = base + (size_t)(2 * p) * strideB;   // batch b0: 12 floats
        size_t o1 = o0 + strideB;                       // batch b1

        // Correctives: 12 consecutive floats per (array,batch), 16B aligned
        float c0[12], c1[12], i0[12], i1[12];
        #pragma unroll
        for (int q4 = 0; q4 < 3; ++q4) {
            *reinterpret_cast<float4*>(c0 + 4*q4) = *reinterpret_cast<const float4*>(pc + o0 + 4*q4);
            *reinterpret_cast<float4*>(c1 + 4*q4) = *reinterpret_cast<const float4*>(pc + o1 + 4*q4);
            *reinterpret_cast<float4*>(i0 + 4*q4) = *reinterpret_cast<const float4*>(ic + o0 + 4*q4);
            *reinterpret_cast<float4*>(i1 + 4*q4) = *reinterpret_cast<const float4*>(ic + o1 + 4*q4);
        }

        float r0[12], r1[12];   // results per batch, 12 consecutive floats
        #pragma unroll
        for (int vv = 0; vv < VPT; ++vv) {
            unsigned long long px = pack2(vc[3*vv+0] + c0[3*vv+0] + i0[3*vv+0],
                                          vc[3*vv+0] + c1[3*vv+0] + i1[3*vv+0]);
            unsigned long long py = pack2(vc[3*vv+1] + c0[3*vv+1] + i0[3*vv+1],
                                          vc[3*vv+1] + c1[3*vv+1] + i1[3*vv+1]);
            unsigned long long pz = pack2(vc[3*vv+2] + c0[3*vv+2] + i0[3*vv+2],
                                          vc[3*vv+2] + c1[3*vv+2] + i1[3*vv+2]);
            #pragma unroll
            for (int r = 0; r < 3; ++r) {
                unsigned long long o = M[vv][4*r + 3];
                o = fma2(M[vv][4*r + 2], pz, o);
                o = fma2(M[vv][4*r + 1], py, o);
                o = fma2(M[vv][4*r + 0], px, o);
                unpack2(o, r0[3*vv + r], r1[3*vv + r]);
            }
        }

        #pragma unroll
        for (int q4 = 0; q4 < 3; ++q4) {
            *reinterpret_cast<float4*>(mesh_out + o0 + 4*q4) = *reinterpret_cast<float4*>(r0 + 4*q4);
            *reinterpret_cast<float4*>(mesh_out + o1 + 4*q4) = *reinterpret_cast<float4*>(r1 + 4*q4);
        }
    }
}

// ---------------------------------------------------------------------------
extern "C" void kernel_launch(void* const* d_in, const int* in_sizes, int n_in,
                              void* d_out, int out_size) {
    const float* joint_euler = (const float*)d_in[0];
    const float* vtx         = (const float*)d_in[1];
    const float* W           = (const float*)d_in[2];
    const float* local_pose  = (const float*)d_in[3];
    const float* gpi         = (const float*)d_in[4];
    const float* sc          = (const float*)d_in[5];
    const float* pc          = (const float*)d_in[6];
    const float* ic          = (const float*)d_in[7];
    const int*   parents     = (const int*)d_in[8];
    float* out = (float*)d_out;

    fk_kernel<<<B_ / BPB, 1024>>>(joint_euler, local_pose, sc, gpi, parents, out);
    dim3 grid((V_ + VT2 - 1) / VT2, B_ / NB);
    skin_kernel<<<grid, VT>>>(vtx, W, pc, ic, out + B_*J_*3);
}